// round 2
// baseline (speedup 1.0000x reference)
#include <cuda_runtime.h>
#include <cstdint>

#define N_NODES 100000
#define E_EDGES 1600000
#define D 64
#define MLP_ROWS 128

// Scratch (device globals: allocation-free per harness rules)
__device__ float g_agg[(size_t)N_NODES * D];
__device__ float g_buf[(size_t)N_NODES * D];
__device__ int   g_ei_is64;   // 1 if edge_index buffer is int64, 0 if int32

// ---------------------------------------------------------------------------
// Probe edge_index dtype: if int64 (little-endian, values < 2^31), every odd
// 32-bit word is 0. For int32 random indices in [0,1e5) that is impossible.
// ---------------------------------------------------------------------------
__global__ void probe_kernel(const int* __restrict__ ei_i32) {
    __shared__ int nz;
    if (threadIdx.x == 0) nz = 0;
    __syncthreads();
    // check odd words 1,3,...,255
    int v = ei_i32[2 * threadIdx.x + 1];
    if (v != 0) atomicOr(&nz, 1);
    __syncthreads();
    if (threadIdx.x == 0) g_ei_is64 = (nz == 0) ? 1 : 0;
}

// ---------------------------------------------------------------------------
// agg = x   (vectorized copy; provides the (1+eps)*x_i self term)
// ---------------------------------------------------------------------------
__global__ void copy_kernel(const float4* __restrict__ x, float4* __restrict__ agg, int n4) {
    int i = blockIdx.x * blockDim.x + threadIdx.x;
    if (i < n4) agg[i] = x[i];
}

// ---------------------------------------------------------------------------
// agg[dst] += x[src]  — 16 threads per edge, one float4 red per thread.
// Consecutive 16 threads handle one edge -> coalesced 256B gather of x[src].
// red.global.add.v4.f32: single no-return vector reduction (sm_90+).
// ---------------------------------------------------------------------------
__global__ void __launch_bounds__(256) scatter_kernel(
    const float* __restrict__ x,
    const void* __restrict__ ei_raw,
    float* __restrict__ agg)
{
    int idx = blockIdx.x * blockDim.x + threadIdx.x;  // < E*16 = 25.6M
    int e = idx >> 4;
    int c = idx & 15;
    if (e >= E_EDGES) return;

    int src, dst;
    if (g_ei_is64) {
        const long long* ei = (const long long*)ei_raw;
        src = (int)__ldg(&ei[e]);
        dst = (int)__ldg(&ei[E_EDGES + e]);
    } else {
        const int* ei = (const int*)ei_raw;
        src = __ldg(&ei[e]);
        dst = __ldg(&ei[E_EDGES + e]);
    }

    float4 v = __ldg((const float4*)(x + (size_t)src * D) + c);
    float* p = agg + (size_t)dst * D + c * 4;
    asm volatile("red.global.add.v4.f32 [%0], {%1,%2,%3,%4};"
                 :: "l"(p), "f"(v.x), "f"(v.y), "f"(v.z), "f"(v.w)
                 : "memory");
}

// ---------------------------------------------------------------------------
// Fused MLP: out = act( act(in @ w1 + b1) [@ w2 + b2] )
// 128 threads = 128 rows per block. Rows staged in padded smem (stride 65:
// bank(t*65+k) = (t+k)%32, conflict-free). Weights broadcast via LDS.128.
// ---------------------------------------------------------------------------
__global__ void __launch_bounds__(MLP_ROWS) mlp_kernel(
    const float* __restrict__ in, float* __restrict__ out,
    const float* __restrict__ w1, const float* __restrict__ b1,
    const float* __restrict__ w2, const float* __restrict__ b2,
    int two_layer)
{
    extern __shared__ float smem[];
    float* sA = smem;                       // [MLP_ROWS][D+1]
    float* sW = smem + MLP_ROWS * (D + 1);  // [D*D]
    float* sB = sW + D * D;                 // [D]

    const int t = threadIdx.x;
    const int row0 = blockIdx.x * MLP_ROWS;

    // Stage rows (coalesced)
    #pragma unroll
    for (int i = t; i < MLP_ROWS * D; i += MLP_ROWS) {
        int r = i >> 6, cc = i & 63;
        int gr = row0 + r;
        sA[r * (D + 1) + cc] = (gr < N_NODES) ? in[(size_t)gr * D + cc] : 0.0f;
    }
    // Stage w1, b1
    #pragma unroll
    for (int i = t; i < D * D; i += MLP_ROWS) sW[i] = w1[i];
    if (t < D) sB[t] = b1[t];
    __syncthreads();

    float acc[D];

    // ---- layer 1 ----
    #pragma unroll
    for (int j = 0; j < D; j++) acc[j] = sB[j];
    #pragma unroll 4
    for (int k = 0; k < D; k++) {
        float a = sA[t * (D + 1) + k];
        #pragma unroll
        for (int j = 0; j < D; j += 4) {
            float4 w = *(const float4*)&sW[k * D + j];
            acc[j]     = fmaf(a, w.x, acc[j]);
            acc[j + 1] = fmaf(a, w.y, acc[j + 1]);
            acc[j + 2] = fmaf(a, w.z, acc[j + 2]);
            acc[j + 3] = fmaf(a, w.w, acc[j + 3]);
        }
    }

    if (two_layer) {
        #pragma unroll
        for (int j = 0; j < D; j++) sA[t * (D + 1) + j] = fmaxf(acc[j], 0.0f);
        __syncthreads();   // layer-1 reads of sW done + sA visible
        #pragma unroll
        for (int i = t; i < D * D; i += MLP_ROWS) sW[i] = w2[i];
        if (t < D) sB[t] = b2[t];
        __syncthreads();

        // ---- layer 2 ----
        #pragma unroll
        for (int j = 0; j < D; j++) acc[j] = sB[j];
        #pragma unroll 4
        for (int k = 0; k < D; k++) {
            float a = sA[t * (D + 1) + k];
            #pragma unroll
            for (int j = 0; j < D; j += 4) {
                float4 w = *(const float4*)&sW[k * D + j];
                acc[j]     = fmaf(a, w.x, acc[j]);
                acc[j + 1] = fmaf(a, w.y, acc[j + 1]);
                acc[j + 2] = fmaf(a, w.z, acc[j + 2]);
                acc[j + 3] = fmaf(a, w.w, acc[j + 3]);
            }
        }
        #pragma unroll
        for (int j = 0; j < D; j++) acc[j] = fmaxf(acc[j], 0.0f);
    }

    const int gr = row0 + t;
    if (gr < N_NODES) {
        #pragma unroll
        for (int j = 0; j < D; j += 4) {
            float4 o = make_float4(acc[j], acc[j + 1], acc[j + 2], acc[j + 3]);
            *(float4*)&out[(size_t)gr * D + j] = o;
        }
    }
}

// ---------------------------------------------------------------------------
extern "C" void kernel_launch(void* const* d_in, const int* in_sizes, int n_in,
                              void* d_out, int out_size)
{
    const float* x   = (const float*)d_in[0];
    const void*  ei  = d_in[1];
    const float* wf  = (const float*)d_in[14];
    const float* bf  = (const float*)d_in[15];

    static float* agg = nullptr;
    static float* buf = nullptr;
    static bool init_done = false;
    static const size_t mlp_smem = (MLP_ROWS * (D + 1) + D * D + D) * sizeof(float);
    if (!init_done) {
        cudaGetSymbolAddress((void**)&agg, g_agg);
        cudaGetSymbolAddress((void**)&buf, g_buf);
        cudaFuncSetAttribute(mlp_kernel, cudaFuncAttributeMaxDynamicSharedMemorySize, (int)mlp_smem);
        init_done = true;
    }

    const int n4 = N_NODES * D / 4;
    const int copy_grid = (n4 + 255) / 256;
    const int scat_grid = (E_EDGES * 16 + 255) / 256;
    const int mlp_grid  = (N_NODES + MLP_ROWS - 1) / MLP_ROWS;

    probe_kernel<<<1, 128>>>((const int*)ei);

    const float* cur = x;
    for (int b = 0; b < 3; b++) {
        const float* w1 = (const float*)d_in[2 + 4 * b + 0];
        const float* b1 = (const float*)d_in[2 + 4 * b + 1];
        const float* w2 = (const float*)d_in[2 + 4 * b + 2];
        const float* b2 = (const float*)d_in[2 + 4 * b + 3];

        copy_kernel<<<copy_grid, 256>>>((const float4*)cur, (float4*)agg, n4);
        scatter_kernel<<<scat_grid, 256>>>(cur, ei, agg);
        mlp_kernel<<<mlp_grid, MLP_ROWS, mlp_smem>>>(agg, buf, w1, b1, w2, b2, 1);
        cur = buf;
    }

    // final linear (no relu)
    mlp_kernel<<<mlp_grid, MLP_ROWS, mlp_smem>>>(cur, (float*)d_out, wf, bf, nullptr, nullptr, 0);
}

// round 3
// speedup vs baseline: 1.1859x; 1.1859x over previous
#include <cuda_runtime.h>
#include <cstdint>

#define N_NODES 100000
#define E_EDGES 1600000
#define D 64
typedef unsigned long long u64;

// Scratch (device globals: allocation-free per harness rules)
__device__ float g_agg[(size_t)N_NODES * D];
__device__ float g_buf[(size_t)N_NODES * D];
__device__ int   g_ei_is64;   // 1 if edge_index buffer is int64, 0 if int32

// ---------------------------------------------------------------------------
// f32x2 packed helpers (Blackwell FFMA2 path — only reachable via PTX)
// ---------------------------------------------------------------------------
__device__ __forceinline__ u64 pack2(float lo, float hi) {
    u64 d; asm("mov.b64 %0, {%1, %2};" : "=l"(d) : "f"(lo), "f"(hi)); return d;
}
__device__ __forceinline__ float2 unpack2(u64 v) {
    float2 f; asm("mov.b64 {%0, %1}, %2;" : "=f"(f.x), "=f"(f.y) : "l"(v)); return f;
}
__device__ __forceinline__ void fma2(u64& d, u64 a, u64 b) {
    asm("fma.rn.f32x2 %0, %1, %2, %0;" : "+l"(d) : "l"(a), "l"(b));
}

// ---------------------------------------------------------------------------
// Probe edge_index dtype: if int64 (values < 2^31), every odd 32-bit word is 0.
// ---------------------------------------------------------------------------
__global__ void probe_kernel(const int* __restrict__ ei_i32) {
    __shared__ int nz;
    if (threadIdx.x == 0) nz = 0;
    __syncthreads();
    int v = ei_i32[2 * threadIdx.x + 1];
    if (v != 0) atomicOr(&nz, 1);
    __syncthreads();
    if (threadIdx.x == 0) g_ei_is64 = (nz == 0) ? 1 : 0;
}

// ---------------------------------------------------------------------------
// agg = x  (only needed once, for the first block's input)
// ---------------------------------------------------------------------------
__global__ void copy_kernel(const float4* __restrict__ x, float4* __restrict__ agg, int n4) {
    int i = blockIdx.x * blockDim.x + threadIdx.x;
    if (i < n4) agg[i] = x[i];
}

// ---------------------------------------------------------------------------
// agg[dst] += x[src]  — 16 threads per edge, one red.global.add.v4.f32 each.
// ---------------------------------------------------------------------------
__global__ void __launch_bounds__(256) scatter_kernel(
    const float* __restrict__ x,
    const void* __restrict__ ei_raw,
    float* __restrict__ agg)
{
    int idx = blockIdx.x * blockDim.x + threadIdx.x;
    int e = idx >> 4;
    int c = idx & 15;
    if (e >= E_EDGES) return;

    int src, dst;
    if (g_ei_is64) {
        const long long* ei = (const long long*)ei_raw;
        src = (int)__ldg(&ei[e]);
        dst = (int)__ldg(&ei[E_EDGES + e]);
    } else {
        const int* ei = (const int*)ei_raw;
        src = __ldg(&ei[e]);
        dst = __ldg(&ei[E_EDGES + e]);
    }

    float4 v = __ldg((const float4*)(x + (size_t)src * D) + c);
    float* p = agg + (size_t)dst * D + c * 4;
    asm volatile("red.global.add.v4.f32 [%0], {%1,%2,%3,%4};"
                 :: "l"(p), "f"(v.x), "f"(v.y), "f"(v.z), "f"(v.w)
                 : "memory");
}

// ---------------------------------------------------------------------------
// Register-tiled MLP, f32x2. 128 threads, tile 128 rows x 64 cols.
// Thread (rg = t>>3, cg = t&7) computes rows r0..r0+7, cols c0..c0+7 -> 32 pairs.
// sA stride 65: scalar A loads hit distinct banks (4 rg/warp, broadcast x8).
// W pairs come straight out of LDS.128 as register aliases (no packing).
// ---------------------------------------------------------------------------
#define SA_STR 65

__device__ __forceinline__ void gemm_tile(const float* sA, const float* sW,
                                          int r0, int c0, u64 acc[8][4])
{
    #pragma unroll 4
    for (int k = 0; k < 64; k++) {
        ulonglong2 wA = *(const ulonglong2*)&sW[k * 64 + c0];
        ulonglong2 wB = *(const ulonglong2*)&sW[k * 64 + c0 + 4];
        #pragma unroll
        for (int i = 0; i < 8; i++) {
            float a = sA[(r0 + i) * SA_STR + k];
            u64 a2 = pack2(a, a);
            fma2(acc[i][0], a2, wA.x);
            fma2(acc[i][1], a2, wA.y);
            fma2(acc[i][2], a2, wB.x);
            fma2(acc[i][3], a2, wB.y);
        }
    }
}

__device__ __forceinline__ void load_bias(const float* b, int c0, u64 bias[4]) {
    float4 v0 = __ldg((const float4*)(b + c0));
    float4 v1 = __ldg((const float4*)(b + c0 + 4));
    bias[0] = pack2(v0.x, v0.y); bias[1] = pack2(v0.z, v0.w);
    bias[2] = pack2(v1.x, v1.y); bias[3] = pack2(v1.z, v1.w);
}

__global__ void __launch_bounds__(128) mlp_kernel(
    const float* __restrict__ in, float* __restrict__ out, float* __restrict__ out2,
    const float* __restrict__ w1, const float* __restrict__ b1,
    const float* __restrict__ w2, const float* __restrict__ b2,
    int two_layer)
{
    extern __shared__ float smem[];
    float* sA = smem;                 // [128][SA_STR]
    float* sW = smem + 128 * SA_STR;  // [64][64]

    const int t  = threadIdx.x;
    const int r0 = (t >> 3) * 8;
    const int c0 = (t & 7) * 8;
    const int row0 = blockIdx.x * 128;

    // Stage A (coalesced float4 loads, scalar smem stores for pad-65 layout)
    #pragma unroll
    for (int i = 0; i < 16; i++) {
        int idx4 = t + i * 128;
        int r = idx4 >> 4, c4 = idx4 & 15;
        int gr = row0 + r;
        float4 v = make_float4(0.f, 0.f, 0.f, 0.f);
        if (gr < N_NODES) v = __ldg((const float4*)(in + (size_t)gr * D) + c4);
        float* p = &sA[r * SA_STR + c4 * 4];
        p[0] = v.x; p[1] = v.y; p[2] = v.z; p[3] = v.w;
    }
    // Stage W1
    #pragma unroll
    for (int i = 0; i < 8; i++)
        *(float4*)&sW[(t + i * 128) * 4] = __ldg((const float4*)w1 + t + i * 128);
    __syncthreads();

    u64 acc[8][4];
    {
        u64 bias[4];
        load_bias(b1, c0, bias);
        #pragma unroll
        for (int i = 0; i < 8; i++)
            #pragma unroll
            for (int p = 0; p < 4; p++) acc[i][p] = bias[p];
    }
    gemm_tile(sA, sW, r0, c0, acc);

    if (two_layer) {
        __syncthreads();   // all layer-1 reads of sA/sW done
        // relu(h1) -> sA (each thread writes its own 8x8 patch)
        #pragma unroll
        for (int i = 0; i < 8; i++) {
            #pragma unroll
            for (int p = 0; p < 4; p++) {
                float2 v = unpack2(acc[i][p]);
                sA[(r0 + i) * SA_STR + c0 + 2 * p]     = fmaxf(v.x, 0.f);
                sA[(r0 + i) * SA_STR + c0 + 2 * p + 1] = fmaxf(v.y, 0.f);
            }
        }
        // Stage W2
        #pragma unroll
        for (int i = 0; i < 8; i++)
            *(float4*)&sW[(t + i * 128) * 4] = __ldg((const float4*)w2 + t + i * 128);
        __syncthreads();

        u64 bias[4];
        load_bias(b2, c0, bias);
        #pragma unroll
        for (int i = 0; i < 8; i++)
            #pragma unroll
            for (int p = 0; p < 4; p++) acc[i][p] = bias[p];
        gemm_tile(sA, sW, r0, c0, acc);
    }

    // Epilogue: (optional outer relu) + store to out, and optionally out2
    #pragma unroll
    for (int i = 0; i < 8; i++) {
        int gr = row0 + r0 + i;
        if (gr < N_NODES) {
            float o[8];
            #pragma unroll
            for (int p = 0; p < 4; p++) {
                float2 v = unpack2(acc[i][p]);
                o[2 * p] = v.x; o[2 * p + 1] = v.y;
            }
            if (two_layer) {
                #pragma unroll
                for (int j = 0; j < 8; j++) o[j] = fmaxf(o[j], 0.f);
            }
            float4 q0 = make_float4(o[0], o[1], o[2], o[3]);
            float4 q1 = make_float4(o[4], o[5], o[6], o[7]);
            size_t off = (size_t)gr * D + c0;
            *(float4*)(out + off)     = q0;
            *(float4*)(out + off + 4) = q1;
            if (out2) {
                *(float4*)(out2 + off)     = q0;
                *(float4*)(out2 + off + 4) = q1;
            }
        }
    }
}

// ---------------------------------------------------------------------------
extern "C" void kernel_launch(void* const* d_in, const int* in_sizes, int n_in,
                              void* d_out, int out_size)
{
    const float* x  = (const float*)d_in[0];
    const void*  ei = d_in[1];
    const float* wf = (const float*)d_in[14];
    const float* bf = (const float*)d_in[15];

    static float* agg = nullptr;
    static float* buf = nullptr;
    static bool init_done = false;
    static const size_t mlp_smem = (128 * SA_STR + D * D) * sizeof(float);
    if (!init_done) {
        cudaGetSymbolAddress((void**)&agg, g_agg);
        cudaGetSymbolAddress((void**)&buf, g_buf);
        cudaFuncSetAttribute(mlp_kernel, cudaFuncAttributeMaxDynamicSharedMemorySize, (int)mlp_smem);
        init_done = true;
    }

    const int n4 = N_NODES * D / 4;
    const int copy_grid = (n4 + 255) / 256;
    const int scat_grid = (E_EDGES * 16 + 255) / 256;
    const int mlp_grid  = (N_NODES + 127) / 128;

    probe_kernel<<<1, 128>>>((const int*)ei);

    // Block 0
    copy_kernel<<<copy_grid, 256>>>((const float4*)x, (float4*)agg, n4);
    scatter_kernel<<<scat_grid, 256>>>(x, ei, agg);
    // mlp writes buf AND re-inits agg = h for next block's scatter (fused copy)
    mlp_kernel<<<mlp_grid, 128, mlp_smem>>>(agg, buf, agg,
        (const float*)d_in[2], (const float*)d_in[3],
        (const float*)d_in[4], (const float*)d_in[5], 1);

    // Block 1
    scatter_kernel<<<scat_grid, 256>>>(buf, ei, agg);
    mlp_kernel<<<mlp_grid, 128, mlp_smem>>>(agg, buf, agg,
        (const float*)d_in[6], (const float*)d_in[7],
        (const float*)d_in[8], (const float*)d_in[9], 1);

    // Block 2
    scatter_kernel<<<scat_grid, 256>>>(buf, ei, agg);
    mlp_kernel<<<mlp_grid, 128, mlp_smem>>>(agg, buf, nullptr,
        (const float*)d_in[10], (const float*)d_in[11],
        (const float*)d_in[12], (const float*)d_in[13], 1);

    // Final linear (no relu)
    mlp_kernel<<<mlp_grid, 128, mlp_smem>>>(buf, (float*)d_out, nullptr,
        wf, bf, nullptr, nullptr, 0);
}

// round 4
// speedup vs baseline: 1.7610x; 1.4850x over previous
#include <cuda_runtime.h>
#include <cstdint>

#define N_NODES 100000
#define E_EDGES 1600000
#define D 64
typedef unsigned long long u64;

// Scratch (device globals: allocation-free per harness rules)
__device__ float g_agg[(size_t)N_NODES * D];
__device__ float g_buf[(size_t)N_NODES * D];
__device__ int   g_deg[N_NODES];     // per-dst degree (histogram)
__device__ int   g_cur[N_NODES];     // fill cursor
__device__ int   g_off[N_NODES];     // exclusive prefix of deg
__device__ int   g_srcs[E_EDGES];    // src indices bucketed by dst
__device__ int   g_part[128];        // scan partials
__device__ int   g_ei_is64;          // 1 if edge_index is int64, 0 if int32

// ---------------------------------------------------------------------------
// f32x2 packed helpers (Blackwell FFMA2 — only reachable via PTX)
// ---------------------------------------------------------------------------
__device__ __forceinline__ u64 pack2(float lo, float hi) {
    u64 d; asm("mov.b64 %0, {%1, %2};" : "=l"(d) : "f"(lo), "f"(hi)); return d;
}
__device__ __forceinline__ float2 unpack2(u64 v) {
    float2 f; asm("mov.b64 {%0, %1}, %2;" : "=f"(f.x), "=f"(f.y) : "l"(v)); return f;
}
__device__ __forceinline__ void fma2(u64& d, u64 a, u64 b) {
    asm("fma.rn.f32x2 %0, %1, %2, %0;" : "+l"(d) : "l"(a), "l"(b));
}

// ---------------------------------------------------------------------------
// Probe edge_index dtype: int64 little-endian with values < 2^31 ->
// every odd 32-bit word is 0. Impossible for 128 random int32 in [0,1e5).
// ---------------------------------------------------------------------------
__global__ void probe_kernel(const int* __restrict__ ei_i32) {
    __shared__ int nz;
    if (threadIdx.x == 0) nz = 0;
    __syncthreads();
    int v = ei_i32[2 * threadIdx.x + 1];
    if (v != 0) atomicOr(&nz, 1);
    __syncthreads();
    if (threadIdx.x == 0) g_ei_is64 = (nz == 0) ? 1 : 0;
}

__device__ __forceinline__ int load_idx(const void* ei_raw, int pos) {
    if (g_ei_is64) return (int)__ldg(&((const long long*)ei_raw)[pos]);
    return __ldg(&((const int*)ei_raw)[pos]);
}

// ---------------------------------------------------------------------------
// Edge bucketing by dst: zero -> histogram -> scan(3) -> fill
// ---------------------------------------------------------------------------
__global__ void zero_kernel() {
    int i = blockIdx.x * blockDim.x + threadIdx.x;
    if (i < N_NODES) { g_deg[i] = 0; g_cur[i] = 0; }
}

__global__ void hist_kernel(const void* __restrict__ ei_raw) {
    int e = blockIdx.x * blockDim.x + threadIdx.x;
    if (e >= E_EDGES) return;
    int dst = load_idx(ei_raw, E_EDGES + e);
    atomicAdd(&g_deg[dst], 1);
}

// 1024-thread blocks, exclusive scan of g_deg -> g_off, block totals -> g_part
__global__ void __launch_bounds__(1024) scan1_kernel() {
    __shared__ int wsum[32];
    int i = blockIdx.x * 1024 + threadIdx.x;
    int v = (i < N_NODES) ? g_deg[i] : 0;
    int lane = threadIdx.x & 31, wid = threadIdx.x >> 5;
    int incl = v;
    #pragma unroll
    for (int d = 1; d < 32; d <<= 1) {
        int n = __shfl_up_sync(~0u, incl, d);
        if (lane >= d) incl += n;
    }
    if (lane == 31) wsum[wid] = incl;
    __syncthreads();
    if (wid == 0) {
        int s = wsum[lane];
        #pragma unroll
        for (int d = 1; d < 32; d <<= 1) {
            int n = __shfl_up_sync(~0u, s, d);
            if (lane >= d) s += n;
        }
        wsum[lane] = s;
    }
    __syncthreads();
    int woff = (wid > 0) ? wsum[wid - 1] : 0;
    if (i < N_NODES) g_off[i] = woff + incl - v;
    if (threadIdx.x == 1023) g_part[blockIdx.x] = woff + incl;
}

__global__ void scan2_kernel(int nparts) {
    if (threadIdx.x == 0) {
        int run = 0;
        for (int i = 0; i < nparts; i++) { int t = g_part[i]; g_part[i] = run; run += t; }
    }
}

__global__ void __launch_bounds__(1024) scan3_kernel() {
    int i = blockIdx.x * 1024 + threadIdx.x;
    if (i < N_NODES) g_off[i] += g_part[blockIdx.x];
}

__global__ void fill_kernel(const void* __restrict__ ei_raw) {
    int e = blockIdx.x * blockDim.x + threadIdx.x;
    if (e >= E_EDGES) return;
    int src = load_idx(ei_raw, e);
    int dst = load_idx(ei_raw, E_EDGES + e);
    int pos = g_off[dst] + atomicAdd(&g_cur[dst], 1);
    g_srcs[pos] = src;
}

// ---------------------------------------------------------------------------
// agg[i] = x[i] + sum_{j in bucket(i)} x[srcs[j]]
// 16 threads per node (float4 column each) -> coalesced 256B row gathers,
// fully coalesced streaming writes. No atomics.
// ---------------------------------------------------------------------------
__global__ void __launch_bounds__(256) aggregate_kernel(
    const float* __restrict__ x, float* __restrict__ agg)
{
    int node = blockIdx.x * 16 + (threadIdx.x >> 4);
    int c = threadIdx.x & 15;
    if (node >= N_NODES) return;

    int beg = __ldg(&g_off[node]);
    int cnt = __ldg(&g_deg[node]);

    float4 v = __ldg((const float4*)(x + (size_t)node * D) + c);

    int j = 0;
    for (; j + 2 <= cnt; j += 2) {
        int s0 = __ldg(&g_srcs[beg + j]);
        int s1 = __ldg(&g_srcs[beg + j + 1]);
        float4 u0 = __ldg((const float4*)(x + (size_t)s0 * D) + c);
        float4 u1 = __ldg((const float4*)(x + (size_t)s1 * D) + c);
        v.x += u0.x + u1.x; v.y += u0.y + u1.y;
        v.z += u0.z + u1.z; v.w += u0.w + u1.w;
    }
    if (j < cnt) {
        int s0 = __ldg(&g_srcs[beg + j]);
        float4 u0 = __ldg((const float4*)(x + (size_t)s0 * D) + c);
        v.x += u0.x; v.y += u0.y; v.z += u0.z; v.w += u0.w;
    }
    *((float4*)(agg + (size_t)node * D) + c) = v;
}

// ---------------------------------------------------------------------------
// Register-tiled MLP, f32x2. 128 threads, tile 128 rows x 64 cols.
// Thread (rg = t>>3, cg = t&7) computes rows r0..r0+7, cols c0..c0+7.
// ---------------------------------------------------------------------------
#define SA_STR 65

__device__ __forceinline__ void gemm_tile(const float* sA, const float* sW,
                                          int r0, int c0, u64 acc[8][4])
{
    #pragma unroll 4
    for (int k = 0; k < 64; k++) {
        ulonglong2 wA = *(const ulonglong2*)&sW[k * 64 + c0];
        ulonglong2 wB = *(const ulonglong2*)&sW[k * 64 + c0 + 4];
        #pragma unroll
        for (int i = 0; i < 8; i++) {
            float a = sA[(r0 + i) * SA_STR + k];
            u64 a2 = pack2(a, a);
            fma2(acc[i][0], a2, wA.x);
            fma2(acc[i][1], a2, wA.y);
            fma2(acc[i][2], a2, wB.x);
            fma2(acc[i][3], a2, wB.y);
        }
    }
}

__device__ __forceinline__ void load_bias(const float* b, int c0, u64 bias[4]) {
    float4 v0 = __ldg((const float4*)(b + c0));
    float4 v1 = __ldg((const float4*)(b + c0 + 4));
    bias[0] = pack2(v0.x, v0.y); bias[1] = pack2(v0.z, v0.w);
    bias[2] = pack2(v1.x, v1.y); bias[3] = pack2(v1.z, v1.w);
}

__global__ void __launch_bounds__(128) mlp_kernel(
    const float* __restrict__ in, float* __restrict__ out,
    const float* __restrict__ w1, const float* __restrict__ b1,
    const float* __restrict__ w2, const float* __restrict__ b2,
    int two_layer)
{
    extern __shared__ float smem[];
    float* sA = smem;                 // [128][SA_STR]
    float* sW = smem + 128 * SA_STR;  // [64][64]

    const int t  = threadIdx.x;
    const int r0 = (t >> 3) * 8;
    const int c0 = (t & 7) * 8;
    const int row0 = blockIdx.x * 128;

    #pragma unroll
    for (int i = 0; i < 16; i++) {
        int idx4 = t + i * 128;
        int r = idx4 >> 4, c4 = idx4 & 15;
        int gr = row0 + r;
        float4 v = make_float4(0.f, 0.f, 0.f, 0.f);
        if (gr < N_NODES) v = __ldg((const float4*)(in + (size_t)gr * D) + c4);
        float* p = &sA[r * SA_STR + c4 * 4];
        p[0] = v.x; p[1] = v.y; p[2] = v.z; p[3] = v.w;
    }
    #pragma unroll
    for (int i = 0; i < 8; i++)
        *(float4*)&sW[(t + i * 128) * 4] = __ldg((const float4*)w1 + t + i * 128);
    __syncthreads();

    u64 acc[8][4];
    {
        u64 bias[4];
        load_bias(b1, c0, bias);
        #pragma unroll
        for (int i = 0; i < 8; i++)
            #pragma unroll
            for (int p = 0; p < 4; p++) acc[i][p] = bias[p];
    }
    gemm_tile(sA, sW, r0, c0, acc);

    if (two_layer) {
        __syncthreads();
        #pragma unroll
        for (int i = 0; i < 8; i++) {
            #pragma unroll
            for (int p = 0; p < 4; p++) {
                float2 v = unpack2(acc[i][p]);
                sA[(r0 + i) * SA_STR + c0 + 2 * p]     = fmaxf(v.x, 0.f);
                sA[(r0 + i) * SA_STR + c0 + 2 * p + 1] = fmaxf(v.y, 0.f);
            }
        }
        #pragma unroll
        for (int i = 0; i < 8; i++)
            *(float4*)&sW[(t + i * 128) * 4] = __ldg((const float4*)w2 + t + i * 128);
        __syncthreads();

        u64 bias[4];
        load_bias(b2, c0, bias);
        #pragma unroll
        for (int i = 0; i < 8; i++)
            #pragma unroll
            for (int p = 0; p < 4; p++) acc[i][p] = bias[p];
        gemm_tile(sA, sW, r0, c0, acc);
    }

    #pragma unroll
    for (int i = 0; i < 8; i++) {
        int gr = row0 + r0 + i;
        if (gr < N_NODES) {
            float o[8];
            #pragma unroll
            for (int p = 0; p < 4; p++) {
                float2 v = unpack2(acc[i][p]);
                o[2 * p] = v.x; o[2 * p + 1] = v.y;
            }
            if (two_layer) {
                #pragma unroll
                for (int j = 0; j < 8; j++) o[j] = fmaxf(o[j], 0.f);
            }
            size_t off = (size_t)gr * D + c0;
            *(float4*)(out + off)     = make_float4(o[0], o[1], o[2], o[3]);
            *(float4*)(out + off + 4) = make_float4(o[4], o[5], o[6], o[7]);
        }
    }
}

// ---------------------------------------------------------------------------
extern "C" void kernel_launch(void* const* d_in, const int* in_sizes, int n_in,
                              void* d_out, int out_size)
{
    const float* x  = (const float*)d_in[0];
    const void*  ei = d_in[1];
    const float* wf = (const float*)d_in[14];
    const float* bf = (const float*)d_in[15];

    static float* agg = nullptr;
    static float* buf = nullptr;
    static bool init_done = false;
    static const size_t mlp_smem = (128 * SA_STR + D * D) * sizeof(float);
    if (!init_done) {
        cudaGetSymbolAddress((void**)&agg, g_agg);
        cudaGetSymbolAddress((void**)&buf, g_buf);
        cudaFuncSetAttribute(mlp_kernel, cudaFuncAttributeMaxDynamicSharedMemorySize, (int)mlp_smem);
        init_done = true;
    }

    const int edge_grid = (E_EDGES + 255) / 256;
    const int node_grid = (N_NODES + 255) / 256;
    const int scan_grid = (N_NODES + 1023) / 1024;   // 98
    const int aggr_grid = (N_NODES + 15) / 16;       // 6250
    const int mlp_grid  = (N_NODES + 127) / 128;

    // --- one-time (per call) edge bucketing by dst ---
    probe_kernel<<<1, 128>>>((const int*)ei);
    zero_kernel<<<node_grid, 256>>>();
    hist_kernel<<<edge_grid, 256>>>(ei);
    scan1_kernel<<<scan_grid, 1024>>>();
    scan2_kernel<<<1, 32>>>(scan_grid);
    scan3_kernel<<<scan_grid, 1024>>>();
    fill_kernel<<<edge_grid, 256>>>(ei);

    // --- 3 GIN blocks ---
    aggregate_kernel<<<aggr_grid, 256>>>(x, agg);
    mlp_kernel<<<mlp_grid, 128, mlp_smem>>>(agg, buf,
        (const float*)d_in[2], (const float*)d_in[3],
        (const float*)d_in[4], (const float*)d_in[5], 1);

    aggregate_kernel<<<aggr_grid, 256>>>(buf, agg);
    mlp_kernel<<<mlp_grid, 128, mlp_smem>>>(agg, buf,
        (const float*)d_in[6], (const float*)d_in[7],
        (const float*)d_in[8], (const float*)d_in[9], 1);

    aggregate_kernel<<<aggr_grid, 256>>>(buf, agg);
    mlp_kernel<<<mlp_grid, 128, mlp_smem>>>(agg, buf,
        (const float*)d_in[10], (const float*)d_in[11],
        (const float*)d_in[12], (const float*)d_in[13], 1);

    // final linear (no relu)
    mlp_kernel<<<mlp_grid, 128, mlp_smem>>>(buf, (float*)d_out,
        wf, bf, nullptr, nullptr, 0);
}

// round 6
// speedup vs baseline: 2.2494x; 1.2773x over previous
#include <cuda_runtime.h>
#include <cuda_bf16.h>
#include <cstdint>

#define N_NODES 100000
#define E_EDGES 1600000
#define D 64

// Scratch (device globals: allocation-free per harness rules)
__device__ float g_agg[(size_t)N_NODES * D];
__device__ float g_buf[(size_t)N_NODES * D];
__device__ int   g_deg[N_NODES];
__device__ int   g_cur[N_NODES];
__device__ int   g_off[N_NODES];
__device__ int   g_srcs[E_EDGES];
__device__ int   g_part[128];
__device__ int   g_ei_is64;

// ===========================================================================
// Edge-index dtype probe + bucketing (validated in R4)
// ===========================================================================
__global__ void probe_kernel(const int* __restrict__ ei_i32) {
    __shared__ int nz;
    if (threadIdx.x == 0) nz = 0;
    __syncthreads();
    int v = ei_i32[2 * threadIdx.x + 1];
    if (v != 0) atomicOr(&nz, 1);
    __syncthreads();
    if (threadIdx.x == 0) g_ei_is64 = (nz == 0) ? 1 : 0;
}

__device__ __forceinline__ int load_idx(const void* ei_raw, int pos) {
    if (g_ei_is64) return (int)__ldg(&((const long long*)ei_raw)[pos]);
    return __ldg(&((const int*)ei_raw)[pos]);
}

__global__ void zero_kernel() {
    int i = blockIdx.x * blockDim.x + threadIdx.x;
    if (i < N_NODES) { g_deg[i] = 0; g_cur[i] = 0; }
}

__global__ void hist_kernel(const void* __restrict__ ei_raw) {
    int e = blockIdx.x * blockDim.x + threadIdx.x;
    if (e >= E_EDGES) return;
    atomicAdd(&g_deg[load_idx(ei_raw, E_EDGES + e)], 1);
}

__global__ void __launch_bounds__(1024) scan1_kernel() {
    __shared__ int wsum[32];
    int i = blockIdx.x * 1024 + threadIdx.x;
    int v = (i < N_NODES) ? g_deg[i] : 0;
    int lane = threadIdx.x & 31, wid = threadIdx.x >> 5;
    int incl = v;
    #pragma unroll
    for (int d = 1; d < 32; d <<= 1) {
        int n = __shfl_up_sync(~0u, incl, d);
        if (lane >= d) incl += n;
    }
    if (lane == 31) wsum[wid] = incl;
    __syncthreads();
    if (wid == 0) {
        int s = wsum[lane];
        #pragma unroll
        for (int d = 1; d < 32; d <<= 1) {
            int n = __shfl_up_sync(~0u, s, d);
            if (lane >= d) s += n;
        }
        wsum[lane] = s;
    }
    __syncthreads();
    int woff = (wid > 0) ? wsum[wid - 1] : 0;
    if (i < N_NODES) g_off[i] = woff + incl - v;
    if (threadIdx.x == 1023) g_part[blockIdx.x] = woff + incl;
}

__global__ void scan2_kernel(int nparts) {
    if (threadIdx.x == 0) {
        int run = 0;
        for (int i = 0; i < nparts; i++) { int t = g_part[i]; g_part[i] = run; run += t; }
    }
}

__global__ void __launch_bounds__(1024) scan3_kernel() {
    int i = blockIdx.x * 1024 + threadIdx.x;
    if (i < N_NODES) g_off[i] += g_part[blockIdx.x];
}

__global__ void fill_kernel(const void* __restrict__ ei_raw) {
    int e = blockIdx.x * blockDim.x + threadIdx.x;
    if (e >= E_EDGES) return;
    int src = load_idx(ei_raw, e);
    int dst = load_idx(ei_raw, E_EDGES + e);
    g_srcs[g_off[dst] + atomicAdd(&g_cur[dst], 1)] = src;
}

// ===========================================================================
// agg[i] = x[i] + sum_{j in bucket(i)} x[srcs[j]]   (no atomics)
// ===========================================================================
__global__ void __launch_bounds__(256) aggregate_kernel(
    const float* __restrict__ x, float* __restrict__ agg)
{
    int node = blockIdx.x * 16 + (threadIdx.x >> 4);
    int c = threadIdx.x & 15;
    if (node >= N_NODES) return;

    int beg = __ldg(&g_off[node]);
    int cnt = __ldg(&g_deg[node]);
    float4 v = __ldg((const float4*)(x + (size_t)node * D) + c);

    int j = 0;
    for (; j + 2 <= cnt; j += 2) {
        int s0 = __ldg(&g_srcs[beg + j]);
        int s1 = __ldg(&g_srcs[beg + j + 1]);
        float4 u0 = __ldg((const float4*)(x + (size_t)s0 * D) + c);
        float4 u1 = __ldg((const float4*)(x + (size_t)s1 * D) + c);
        v.x += u0.x + u1.x; v.y += u0.y + u1.y;
        v.z += u0.z + u1.z; v.w += u0.w + u1.w;
    }
    if (j < cnt) {
        int s0 = __ldg(&g_srcs[beg + j]);
        float4 u0 = __ldg((const float4*)(x + (size_t)s0 * D) + c);
        v.x += u0.x; v.y += u0.y; v.z += u0.z; v.w += u0.w;
    }
    *((float4*)(agg + (size_t)node * D) + c) = v;
}

// ===========================================================================
// Tensor-core MLP via mma.sync.m16n8k16 bf16 (base PTX ISA — sm_103-safe).
// bf16 2-term split, 3 passes (hi*hi + hi*lo + lo*hi), fp32 accum.
// CTA = 128 threads / 128 rows. Warp w owns rows 32w..32w+31 (2 m16 tiles),
// all 64 cols (8 n8 tiles), K=64 (4 k16 steps).
// Smem rows padded to 72 halves (36 words): frag word = row*36 + tig + k0/2
// -> lanes (8 rows x 4 tig) hit 32 distinct banks.
// ===========================================================================
#define SR 72   // smem row stride in bf16 elements (A and B tiles)

#define SM_BIAS1 0
#define SM_BIAS2 256
#define SM_AHI   512
#define SM_ALO   (SM_AHI + 128 * SR * 2)   // 512 + 18432
#define SM_BHI   (SM_ALO + 128 * SR * 2)   // + 18432
#define SM_BLO   (SM_BHI + 64 * SR * 2)    // + 9216
#define SM_TOT   (SM_BLO + 64 * SR * 2)    // 55808

__device__ __forceinline__ void split1(float x, float& h, float& l) {
    __nv_bfloat16 bh = __float2bfloat16_rn(x);
    h = __bfloat162float(bh);
    l = x - h;
}
__device__ __forceinline__ uint32_t packbf2(float a, float b) {
    __nv_bfloat162 h = __floats2bfloat162_rn(a, b);
    return *(uint32_t*)&h;
}

__device__ __forceinline__ void mma16816(float c[4], uint32_t a0, uint32_t a1,
                                         uint32_t a2, uint32_t a3,
                                         uint32_t b0, uint32_t b1) {
    asm volatile(
        "mma.sync.aligned.m16n8k16.row.col.f32.bf16.bf16.f32 "
        "{%0,%1,%2,%3}, {%4,%5,%6,%7}, {%8,%9}, {%0,%1,%2,%3};"
        : "+f"(c[0]), "+f"(c[1]), "+f"(c[2]), "+f"(c[3])
        : "r"(a0), "r"(a1), "r"(a2), "r"(a3), "r"(b0), "r"(b1));
}

// One K=64 pass: c += A(128x64, warp's 32 rows) @ B(64n x 64k)^T
__device__ __forceinline__ void gemm_pass(const __nv_bfloat16* __restrict__ A,
                                          const __nv_bfloat16* __restrict__ B,
                                          float c[2][8][4], int m0, int g, int tig)
{
    #pragma unroll
    for (int ks = 0; ks < 4; ks++) {
        const int k0 = ks * 16;
        uint32_t a[2][4];
        #pragma unroll
        for (int mt = 0; mt < 2; mt++) {
            const __nv_bfloat16* p0 = A + (m0 + mt * 16 + g) * SR + k0 + tig * 2;
            const __nv_bfloat16* p1 = p0 + 8 * SR;
            a[mt][0] = *(const uint32_t*)p0;       // rows g,    k0..k0+7
            a[mt][1] = *(const uint32_t*)p1;       // rows g+8,  k0..k0+7
            a[mt][2] = *(const uint32_t*)(p0 + 8); // rows g,    k0+8..k0+15
            a[mt][3] = *(const uint32_t*)(p1 + 8); // rows g+8,  k0+8..k0+15
        }
        #pragma unroll
        for (int nt = 0; nt < 8; nt++) {
            const __nv_bfloat16* pb = B + (nt * 8 + g) * SR + k0 + tig * 2;
            uint32_t b0 = *(const uint32_t*)pb;
            uint32_t b1 = *(const uint32_t*)(pb + 8);
            mma16816(c[0][nt], a[0][0], a[0][1], a[0][2], a[0][3], b0, b1);
            mma16816(c[1][nt], a[1][0], a[1][1], a[1][2], a[1][3], b0, b1);
        }
    }
}

// stage W^T (thread t<64 = row k of W): Wt[n][k] hi/lo bf16
__device__ __forceinline__ void stage_w(const float* __restrict__ w,
                                        __nv_bfloat16* bhi, __nv_bfloat16* blo, int k)
{
    #pragma unroll 4
    for (int c4 = 0; c4 < 16; c4++) {
        float4 v = __ldg((const float4*)(w + k * 64) + c4);
        float fv[4] = {v.x, v.y, v.z, v.w};
        #pragma unroll
        for (int j = 0; j < 4; j++) {
            int n = c4 * 4 + j;
            float h, l; split1(fv[j], h, l);
            bhi[n * SR + k] = __float2bfloat16_rn(h);
            blo[n * SR + k] = __float2bfloat16_rn(l);
        }
    }
}

__global__ void __launch_bounds__(128) mlp_tc_kernel(
    const float* __restrict__ in, float* __restrict__ out,
    const float* __restrict__ w1, const float* __restrict__ b1,
    const float* __restrict__ w2, const float* __restrict__ b2,
    int two_layer)
{
    extern __shared__ char smem[];
    float* sB1 = (float*)(smem + SM_BIAS1);
    float* sB2 = (float*)(smem + SM_BIAS2);
    __nv_bfloat16* sAhi = (__nv_bfloat16*)(smem + SM_AHI);
    __nv_bfloat16* sAlo = (__nv_bfloat16*)(smem + SM_ALO);
    __nv_bfloat16* sBhi = (__nv_bfloat16*)(smem + SM_BHI);
    __nv_bfloat16* sBlo = (__nv_bfloat16*)(smem + SM_BLO);

    const int t = threadIdx.x;
    const int warp = t >> 5, lane = t & 31;
    const int g = lane >> 2, tig = lane & 3;
    const int m0 = warp * 32;
    const int row0 = blockIdx.x * 128;

    // ---- stage A (hi/lo split): 2048 float4 reads, 16 iters ----
    #pragma unroll
    for (int i = 0; i < 16; i++) {
        int idx4 = t + i * 128;
        int r = idx4 >> 4, c4 = idx4 & 15;
        int gr = row0 + r;
        float4 v = make_float4(0.f, 0.f, 0.f, 0.f);
        if (gr < N_NODES) v = __ldg((const float4*)(in + (size_t)gr * D) + c4);
        float h0, l0, h1, l1, h2, l2, h3, l3;
        split1(v.x, h0, l0); split1(v.y, h1, l1);
        split1(v.z, h2, l2); split1(v.w, h3, l3);
        uint32_t* ph = (uint32_t*)(sAhi + r * SR + c4 * 4);
        uint32_t* pl = (uint32_t*)(sAlo + r * SR + c4 * 4);
        ph[0] = packbf2(h0, h1); ph[1] = packbf2(h2, h3);
        pl[0] = packbf2(l0, l1); pl[1] = packbf2(l2, l3);
    }
    // ---- stage W1^T (t<64) + biases ----
    if (t < 64) stage_w(w1, sBhi, sBlo, t);
    else if (t < 80) ((float4*)sB1)[t - 64] = __ldg((const float4*)b1 + (t - 64));
    else if (t < 96 && two_layer) ((float4*)sB2)[t - 80] = __ldg((const float4*)b2 + (t - 80));
    __syncthreads();

    float c[2][8][4];
    #pragma unroll
    for (int mt = 0; mt < 2; mt++)
        #pragma unroll
        for (int nt = 0; nt < 8; nt++)
            #pragma unroll
            for (int j = 0; j < 4; j++) c[mt][nt][j] = 0.f;

    gemm_pass(sAhi, sBhi, c, m0, g, tig);
    gemm_pass(sAhi, sBlo, c, m0, g, tig);
    gemm_pass(sAlo, sBhi, c, m0, g, tig);

    if (two_layer) {
        // h1 = relu(c + b1) -> back into own A rows (hi/lo), then stage W2
        #pragma unroll
        for (int mt = 0; mt < 2; mt++) {
            int r0 = m0 + mt * 16 + g;
            #pragma unroll
            for (int nt = 0; nt < 8; nt++) {
                int cb = nt * 8 + tig * 2;
                float o0 = fmaxf(c[mt][nt][0] + sB1[cb],     0.f);
                float o1 = fmaxf(c[mt][nt][1] + sB1[cb + 1], 0.f);
                float o2 = fmaxf(c[mt][nt][2] + sB1[cb],     0.f);
                float o3 = fmaxf(c[mt][nt][3] + sB1[cb + 1], 0.f);
                float h, l, h2v, l2v;
                split1(o0, h, l); split1(o1, h2v, l2v);
                *(uint32_t*)(sAhi + r0 * SR + cb) = packbf2(h, h2v);
                *(uint32_t*)(sAlo + r0 * SR + cb) = packbf2(l, l2v);
                split1(o2, h, l); split1(o3, h2v, l2v);
                *(uint32_t*)(sAhi + (r0 + 8) * SR + cb) = packbf2(h, h2v);
                *(uint32_t*)(sAlo + (r0 + 8) * SR + cb) = packbf2(l, l2v);
            }
        }
        __syncthreads();                 // all warps done reading W1
        if (t < 64) stage_w(w2, sBhi, sBlo, t);
        __syncthreads();                 // W2 + h1 visible

        #pragma unroll
        for (int mt = 0; mt < 2; mt++)
            #pragma unroll
            for (int nt = 0; nt < 8; nt++)
                #pragma unroll
                for (int j = 0; j < 4; j++) c[mt][nt][j] = 0.f;

        gemm_pass(sAhi, sBhi, c, m0, g, tig);
        gemm_pass(sAhi, sBlo, c, m0, g, tig);
        gemm_pass(sAlo, sBhi, c, m0, g, tig);
    }

    // ---- epilogue: bias (+ relu for GIN block), store ----
    const float* bias = two_layer ? sB2 : sB1;
    #pragma unroll
    for (int mt = 0; mt < 2; mt++) {
        int r0 = row0 + m0 + mt * 16 + g;
        int r1 = r0 + 8;
        #pragma unroll
        for (int nt = 0; nt < 8; nt++) {
            int cb = nt * 8 + tig * 2;
            float o0 = c[mt][nt][0] + bias[cb];
            float o1 = c[mt][nt][1] + bias[cb + 1];
            float o2 = c[mt][nt][2] + bias[cb];
            float o3 = c[mt][nt][3] + bias[cb + 1];
            if (two_layer) {
                o0 = fmaxf(o0, 0.f); o1 = fmaxf(o1, 0.f);
                o2 = fmaxf(o2, 0.f); o3 = fmaxf(o3, 0.f);
            }
            if (r0 < N_NODES) *(float2*)(out + (size_t)r0 * D + cb) = make_float2(o0, o1);
            if (r1 < N_NODES) *(float2*)(out + (size_t)r1 * D + cb) = make_float2(o2, o3);
        }
    }
}

// ===========================================================================
extern "C" void kernel_launch(void* const* d_in, const int* in_sizes, int n_in,
                              void* d_out, int out_size)
{
    const float* x  = (const float*)d_in[0];
    const void*  ei = d_in[1];
    const float* wf = (const float*)d_in[14];
    const float* bf = (const float*)d_in[15];

    static float* agg = nullptr;
    static float* buf = nullptr;
    static bool init_done = false;
    if (!init_done) {
        cudaGetSymbolAddress((void**)&agg, g_agg);
        cudaGetSymbolAddress((void**)&buf, g_buf);
        cudaFuncSetAttribute(mlp_tc_kernel, cudaFuncAttributeMaxDynamicSharedMemorySize, SM_TOT);
        init_done = true;
    }

    const int edge_grid = (E_EDGES + 255) / 256;
    const int node_grid = (N_NODES + 255) / 256;
    const int scan_grid = (N_NODES + 1023) / 1024;
    const int aggr_grid = (N_NODES + 15) / 16;
    const int mlp_grid  = (N_NODES + 127) / 128;

    probe_kernel<<<1, 128>>>((const int*)ei);
    zero_kernel<<<node_grid, 256>>>();
    hist_kernel<<<edge_grid, 256>>>(ei);
    scan1_kernel<<<scan_grid, 1024>>>();
    scan2_kernel<<<1, 32>>>(scan_grid);
    scan3_kernel<<<scan_grid, 1024>>>();
    fill_kernel<<<edge_grid, 256>>>(ei);

    aggregate_kernel<<<aggr_grid, 256>>>(x, agg);
    mlp_tc_kernel<<<mlp_grid, 128, SM_TOT>>>(agg, buf,
        (const float*)d_in[2], (const float*)d_in[3],
        (const float*)d_in[4], (const float*)d_in[5], 1);

    aggregate_kernel<<<aggr_grid, 256>>>(buf, agg);
    mlp_tc_kernel<<<mlp_grid, 128, SM_TOT>>>(agg, buf,
        (const float*)d_in[6], (const float*)d_in[7],
        (const float*)d_in[8], (const float*)d_in[9], 1);

    aggregate_kernel<<<aggr_grid, 256>>>(buf, agg);
    mlp_tc_kernel<<<mlp_grid, 128, SM_TOT>>>(agg, buf,
        (const float*)d_in[10], (const float*)d_in[11],
        (const float*)d_in[12], (const float*)d_in[13], 1);

    mlp_tc_kernel<<<mlp_grid, 128, SM_TOT>>>(buf, (float*)d_out,
        wf, bf, nullptr, nullptr, 0);
}